// round 1
// baseline (speedup 1.0000x reference)
#include <cuda_runtime.h>
#include <cuda_bf16.h>
#include <cstdint>

#define BB 2
#define CC 256
#define NN 4096
#define NEGBIG (-3.4028234e38f)

// ---------------- scratch (device globals; no runtime allocation) -------------
__device__ float g_F[(size_t)BB * NN * CC];   // [b, n, c]
__device__ float g_G[(size_t)BB * NN * CC];   // [b, n, c]
__device__ float g_H[(size_t)BB * NN * CC];   // [b, m, c]
__device__ float g_O[(size_t)BB * NN * CC];   // [b, n, c]
__device__ float g_S[(size_t)BB * NN * NN];   // [b, n, m]  (134 MB)
__device__ int   g_idx[BB * NN];
__device__ float g_mean[2 * BB * CC];
__device__ float g_istd[2 * BB * CC];

// ---------------- helpers -----------------------------------------------------
__device__ __forceinline__ float int_or_float(int v) {
    // t1/t2 may arrive as int32 or as float bits; small ints are ints.
    return (v >= -100000 && v <= 100000) ? (float)v : __int_as_float(v);
}

__device__ __forceinline__ int idx8(int base4, int k) {
    return (k < 4) ? (base4 + k) : (64 + base4 + (k - 4));
}

__device__ __forceinline__ void mm_tile(const float (&As)[8][128],
                                        const float (&Bs)[8][128],
                                        int row4, int col4, float (&acc)[8][8]) {
#pragma unroll
    for (int kk = 0; kk < 8; ++kk) {
        float a[8], b[8];
#pragma unroll
        for (int i = 0; i < 4; ++i) { a[i] = As[kk][row4 + i]; a[4 + i] = As[kk][64 + row4 + i]; }
#pragma unroll
        for (int j = 0; j < 4; ++j) { b[j] = Bs[kk][col4 + j]; b[4 + j] = Bs[kk][64 + col4 + j]; }
#pragma unroll
        for (int i = 0; i < 8; ++i)
#pragma unroll
            for (int j = 0; j < 8; ++j) acc[i][j] += a[i] * b[j];
    }
}

// ---------------- stats: per (b,c) mean / inv-std (ddof=1) --------------------
__global__ void __launch_bounds__(256) stats_kernel(const float* __restrict__ x,
                                                    float* __restrict__ meanv,
                                                    float* __restrict__ istdv) {
    int row = blockIdx.x;                 // b*CC + c
    const float* p = x + (size_t)row * NN;
    int t = threadIdx.x;
    float s = 0.f, s2 = 0.f;
    for (int i = t; i < NN; i += 256) { float v = p[i]; s += v; s2 += v * v; }
    __shared__ float sh1[256], sh2[256];
    sh1[t] = s; sh2[t] = s2; __syncthreads();
    for (int o = 128; o > 0; o >>= 1) {
        if (t < o) { sh1[t] += sh1[t + o]; sh2[t] += sh2[t + o]; }
        __syncthreads();
    }
    if (t == 0) {
        float m = sh1[0] / NN;
        float var = (sh2[0] - (float)NN * m * m) / (float)(NN - 1);
        meanv[row] = m;
        istdv[row] = rsqrtf(var + 1e-5f);
    }
}

// ---------------- F/G/H GEMM: out[b,n,c] = sum_k W[c,k]*norm(x[b,k,n]) + bias[c]
__global__ void __launch_bounds__(256) gemm_fgh(const float* __restrict__ x,
                                                const float* __restrict__ W,
                                                const float* __restrict__ bias,
                                                const float* __restrict__ meanv,
                                                const float* __restrict__ istdv,
                                                float* __restrict__ out,
                                                int use_norm) {
    const int b  = blockIdx.z;
    const int n0 = blockIdx.x * 128;
    const int c0 = blockIdx.y * 128;
    __shared__ float As[8][128];   // As[k][n]
    __shared__ float Bs[8][128];   // Bs[k][c]
    const int t = threadIdx.x, tx = t & 15, ty = t >> 4;
    const int row4 = ty * 4, col4 = tx * 4;     // rows=n, cols=c
    const int ai = t & 127, ak0 = t >> 7;       // A loader
    const int lr = t >> 1, lq = (t & 1) * 4;    // B loader (float4)
    const float* xb = x + (size_t)b * CC * NN;
    const float* mb = meanv + b * CC;
    const float* ib = istdv + b * CC;

    float acc[8][8];
#pragma unroll
    for (int i = 0; i < 8; ++i)
#pragma unroll
        for (int j = 0; j < 8; ++j) acc[i][j] = 0.f;

    for (int k0 = 0; k0 < CC; k0 += 8) {
#pragma unroll
        for (int u = 0; u < 4; ++u) {
            int kk = ak0 + 2 * u;
            float v = xb[(size_t)(k0 + kk) * NN + n0 + ai];
            if (use_norm) v = (v - mb[k0 + kk]) * ib[k0 + kk];
            As[kk][ai] = v;
        }
        float4 wv = *(const float4*)(W + (size_t)(c0 + lr) * CC + k0 + lq);
        Bs[lq + 0][lr] = wv.x; Bs[lq + 1][lr] = wv.y;
        Bs[lq + 2][lr] = wv.z; Bs[lq + 3][lr] = wv.w;
        __syncthreads();
        mm_tile(As, Bs, row4, col4, acc);
        __syncthreads();
    }
#pragma unroll
    for (int i = 0; i < 8; ++i) {
        int n = n0 + idx8(row4, i);
        float* op = out + ((size_t)b * NN + n) * CC + c0;
#pragma unroll
        for (int j = 0; j < 8; ++j) {
            int cj = idx8(col4, j);
            op[cj] = acc[i][j] + bias[c0 + cj];
        }
    }
}

// ---------------- score GEMM: S[b,n,m] = sum_c F[b,n,c]*G[b,m,c] --------------
__global__ void __launch_bounds__(256) gemm_score(const float* __restrict__ Fm,
                                                  const float* __restrict__ Gm,
                                                  float* __restrict__ S) {
    const int b  = blockIdx.z;
    const int n0 = blockIdx.y * 128;
    const int m0 = blockIdx.x * 128;
    const float* A = Fm + (size_t)b * NN * CC;
    const float* B = Gm + (size_t)b * NN * CC;
    __shared__ float As[8][128];   // As[k][n]
    __shared__ float Bs[8][128];   // Bs[k][m]
    const int t = threadIdx.x, tx = t & 15, ty = t >> 4;
    const int row4 = ty * 4, col4 = tx * 4;
    const int lr = t >> 1, lq = (t & 1) * 4;

    float acc[8][8];
#pragma unroll
    for (int i = 0; i < 8; ++i)
#pragma unroll
        for (int j = 0; j < 8; ++j) acc[i][j] = 0.f;

    for (int k0 = 0; k0 < CC; k0 += 8) {
        float4 av = *(const float4*)(A + (size_t)(n0 + lr) * CC + k0 + lq);
        float4 bv = *(const float4*)(B + (size_t)(m0 + lr) * CC + k0 + lq);
        As[lq + 0][lr] = av.x; As[lq + 1][lr] = av.y; As[lq + 2][lr] = av.z; As[lq + 3][lr] = av.w;
        Bs[lq + 0][lr] = bv.x; Bs[lq + 1][lr] = bv.y; Bs[lq + 2][lr] = bv.z; Bs[lq + 3][lr] = bv.w;
        __syncthreads();
        mm_tile(As, Bs, row4, col4, acc);
        __syncthreads();
    }
    float* Sp = S + (size_t)b * NN * NN;
#pragma unroll
    for (int i = 0; i < 8; ++i) {
        int n = n0 + idx8(row4, i);
        float* rp = Sp + (size_t)n * NN + m0;
        float4 v0 = make_float4(acc[i][0], acc[i][1], acc[i][2], acc[i][3]);
        float4 v1 = make_float4(acc[i][4], acc[i][5], acc[i][6], acc[i][7]);
        *(float4*)(rp + col4)      = v0;
        *(float4*)(rp + 64 + col4) = v1;
    }
}

// ---------------- masked row softmax (in place) -------------------------------
__global__ void __launch_bounds__(256) softmax_kernel(float* __restrict__ S,
                                                      const float* __restrict__ mask) {
    const int bn = blockIdx.x;
    const int n  = bn & (NN - 1);
    float* row = S + (size_t)bn * NN;
    const float* mrow = mask + (size_t)n * NN;
    const int t = threadIdx.x;
    float v[16];
    float mx = NEGBIG;
#pragma unroll
    for (int r = 0; r < 16; ++r) {
        int i = t + r * 256;
        float sv = row[i];
        v[r] = (mrow[i] < 0.5f) ? NEGBIG : sv;
        mx = fmaxf(mx, v[r]);
    }
    __shared__ float red[256];
    red[t] = mx; __syncthreads();
    for (int o = 128; o > 0; o >>= 1) {
        if (t < o) red[t] = fmaxf(red[t], red[t + o]);
        __syncthreads();
    }
    mx = red[0]; __syncthreads();
    float sum = 0.f;
#pragma unroll
    for (int r = 0; r < 16; ++r) {
        float e = (v[r] > -1e37f) ? expf(v[r] - mx) : 0.f;
        v[r] = e; sum += e;
    }
    red[t] = sum; __syncthreads();
    for (int o = 128; o > 0; o >>= 1) {
        if (t < o) red[t] += red[t + o];
        __syncthreads();
    }
    float inv = 1.f / red[0];
#pragma unroll
    for (int r = 0; r < 16; ++r) row[t + r * 256] = v[r] * inv;
}

// ---------------- masked row argmax -------------------------------------------
__global__ void __launch_bounds__(256) argmax_kernel(const float* __restrict__ S,
                                                     const float* __restrict__ mask,
                                                     int* __restrict__ idxv) {
    const int bn = blockIdx.x;
    const int n  = bn & (NN - 1);
    const float* row = S + (size_t)bn * NN;
    const float* mrow = mask + (size_t)n * NN;
    const int t = threadIdx.x;
    float best = -INFINITY; int bi = 0;
#pragma unroll
    for (int r = 0; r < 16; ++r) {
        int i = t + r * 256;
        float sv = (mrow[i] < 0.5f) ? NEGBIG : row[i];
        if (sv > best || (sv == best && i < bi)) { best = sv; bi = i; }
    }
    __shared__ float rv[256];
    __shared__ int   ri[256];
    rv[t] = best; ri[t] = bi; __syncthreads();
    for (int o = 128; o > 0; o >>= 1) {
        if (t < o) {
            if (rv[t + o] > rv[t] || (rv[t + o] == rv[t] && ri[t + o] < ri[t])) {
                rv[t] = rv[t + o]; ri[t] = ri[t + o];
            }
        }
        __syncthreads();
    }
    if (t == 0) idxv[bn] = ri[0];
}

// ---------------- A·V GEMM: O[b,n,c] = sum_m A[b,n,m]*H[b,m,c] ----------------
__global__ void __launch_bounds__(256) gemm_av(const float* __restrict__ S,
                                               const float* __restrict__ Hm,
                                               float* __restrict__ O) {
    const int b  = blockIdx.z;
    const int n0 = blockIdx.y * 128;
    const int c0 = blockIdx.x * 128;
    const float* A = S + (size_t)b * NN * NN;
    const float* B = Hm + (size_t)b * NN * CC;
    __shared__ float As[8][128];   // As[k][n]
    __shared__ float Bs[8][128];   // Bs[k][c]
    const int t = threadIdx.x, tx = t & 15, ty = t >> 4;
    const int row4 = ty * 4, col4 = tx * 4;
    const int lr = t >> 1, lq = (t & 1) * 4;
    const int ai = t & 127, ak0 = t >> 7;

    float acc[8][8];
#pragma unroll
    for (int i = 0; i < 8; ++i)
#pragma unroll
        for (int j = 0; j < 8; ++j) acc[i][j] = 0.f;

    for (int k0 = 0; k0 < NN; k0 += 8) {
        float4 av = *(const float4*)(A + (size_t)(n0 + lr) * NN + k0 + lq);
        As[lq + 0][lr] = av.x; As[lq + 1][lr] = av.y; As[lq + 2][lr] = av.z; As[lq + 3][lr] = av.w;
#pragma unroll
        for (int u = 0; u < 4; ++u) {
            int kk = ak0 + 2 * u;
            Bs[kk][ai] = B[(size_t)(k0 + kk) * CC + c0 + ai];
        }
        __syncthreads();
        mm_tile(As, Bs, row4, col4, acc);
        __syncthreads();
    }
#pragma unroll
    for (int i = 0; i < 8; ++i) {
        int n = n0 + idx8(row4, i);
        float* op = O + ((size_t)b * NN + n) * CC + c0;
        float4 v0 = make_float4(acc[i][0], acc[i][1], acc[i][2], acc[i][3]);
        float4 v1 = make_float4(acc[i][4], acc[i][5], acc[i][6], acc[i][7]);
        *(float4*)(op + col4)      = v0;
        *(float4*)(op + 64 + col4) = v1;
    }
}

// ---------------- combine: V[b,n,c] = t1*O[b,n,c] + t2*H[b,idx[b,n],c] --------
__global__ void __launch_bounds__(256) combine_kernel(const float* __restrict__ O,
                                                      const float* __restrict__ Hm,
                                                      const int* __restrict__ idxv,
                                                      const int* __restrict__ t1p,
                                                      const int* __restrict__ t2p,
                                                      float* __restrict__ V) {
    const int bn = blockIdx.x;
    const int b  = bn >> 12;
    const float t1f = int_or_float(t1p[0]);
    const float t2f = int_or_float(t2p[0]);
    const int id = idxv[bn];
    const float* op = O + (size_t)bn * CC;
    const float* hp = Hm + ((size_t)b * NN + id) * CC;
    float* vp = V + (size_t)bn * CC;
    for (int c = threadIdx.x; c < CC; c += 256)
        vp[c] = t1f * op[c] + t2f * hp[c];
}

// ---------------- final: out[b,c,n] = sum_k Wo[c,k]*V[b,n,k] + t12*bo[c] + content
__global__ void __launch_bounds__(256) gemm_final(const float* __restrict__ Wo,
                                                  const float* __restrict__ V,
                                                  const float* __restrict__ bo,
                                                  const float* __restrict__ content,
                                                  const int* __restrict__ t1p,
                                                  const int* __restrict__ t2p,
                                                  float* __restrict__ out) {
    const int b  = blockIdx.z;
    const int n0 = blockIdx.x * 128;
    const int c0 = blockIdx.y * 128;
    __shared__ float As[8][128];   // As[k][c]
    __shared__ float Bs[8][128];   // Bs[k][n]
    const int t = threadIdx.x, tx = t & 15, ty = t >> 4;
    const int row4 = ty * 4, col4 = tx * 4;   // rows=c, cols=n
    const int lr = t >> 1, lq = (t & 1) * 4;
    const float* Vb = V + (size_t)b * NN * CC;

    float acc[8][8];
#pragma unroll
    for (int i = 0; i < 8; ++i)
#pragma unroll
        for (int j = 0; j < 8; ++j) acc[i][j] = 0.f;

    for (int k0 = 0; k0 < CC; k0 += 8) {
        float4 av = *(const float4*)(Wo + (size_t)(c0 + lr) * CC + k0 + lq);
        float4 bv = *(const float4*)(Vb + (size_t)(n0 + lr) * CC + k0 + lq);
        As[lq + 0][lr] = av.x; As[lq + 1][lr] = av.y; As[lq + 2][lr] = av.z; As[lq + 3][lr] = av.w;
        Bs[lq + 0][lr] = bv.x; Bs[lq + 1][lr] = bv.y; Bs[lq + 2][lr] = bv.z; Bs[lq + 3][lr] = bv.w;
        __syncthreads();
        mm_tile(As, Bs, row4, col4, acc);
        __syncthreads();
    }
    const float t12 = int_or_float(t1p[0]) + int_or_float(t2p[0]);
#pragma unroll
    for (int i = 0; i < 8; ++i) {
        int c = c0 + idx8(row4, i);
        float bb = t12 * bo[c];
        float* op = out + ((size_t)b * CC + c) * NN + n0;
        const float* cp = content + ((size_t)b * CC + c) * NN + n0;
        float4 c0v = *(const float4*)(cp + col4);
        float4 c1v = *(const float4*)(cp + 64 + col4);
        float4 v0 = make_float4(acc[i][0] + bb + c0v.x, acc[i][1] + bb + c0v.y,
                                acc[i][2] + bb + c0v.z, acc[i][3] + bb + c0v.w);
        float4 v1 = make_float4(acc[i][4] + bb + c1v.x, acc[i][5] + bb + c1v.y,
                                acc[i][6] + bb + c1v.z, acc[i][7] + bb + c1v.w);
        *(float4*)(op + col4)      = v0;
        *(float4*)(op + 64 + col4) = v1;
    }
}

// ---------------- launch -------------------------------------------------------
extern "C" void kernel_launch(void* const* d_in, const int* in_sizes, int n_in,
                              void* d_out, int out_size) {
    (void)in_sizes; (void)n_in; (void)out_size;
    const float* content     = (const float*)d_in[0];
    const float* style       = (const float*)d_in[1];
    const float* content_sem = (const float*)d_in[2];
    const float* style_sem   = (const float*)d_in[3];
    /* d_in[4] = map_32 (unused: h*w == 4096 -> map_64 branch) */
    const float* map64       = (const float*)d_in[5];
    const int*   t1p         = (const int*)d_in[6];
    const int*   t2p         = (const int*)d_in[7];
    const float* Wf = (const float*)d_in[8];   const float* bf = (const float*)d_in[9];
    const float* Wg = (const float*)d_in[10];  const float* bg = (const float*)d_in[11];
    const float* Wh = (const float*)d_in[12];  const float* bh = (const float*)d_in[13];
    const float* Wo = (const float*)d_in[14];  const float* bo = (const float*)d_in[15];
    float* out = (float*)d_out;

    float *pF, *pG, *pH, *pO, *pS, *pMean, *pIstd; int* pIdx;
    cudaGetSymbolAddress((void**)&pF, g_F);
    cudaGetSymbolAddress((void**)&pG, g_G);
    cudaGetSymbolAddress((void**)&pH, g_H);
    cudaGetSymbolAddress((void**)&pO, g_O);
    cudaGetSymbolAddress((void**)&pS, g_S);
    cudaGetSymbolAddress((void**)&pMean, g_mean);
    cudaGetSymbolAddress((void**)&pIstd, g_istd);
    cudaGetSymbolAddress((void**)&pIdx, g_idx);

    const dim3 gFGH(NN / 128, CC / 128, BB);
    const dim3 gSCORE(NN / 128, NN / 128, BB);
    const dim3 gAV(CC / 128, NN / 128, BB);

    // ---- SCA branch (semantic features, soft attention) ----
    stats_kernel<<<BB * CC, 256>>>(content_sem, pMean, pIstd);
    stats_kernel<<<BB * CC, 256>>>(style_sem, pMean + BB * CC, pIstd + BB * CC);
    gemm_fgh<<<gFGH, 256>>>(content_sem, Wf, bf, pMean, pIstd, pF, 1);
    gemm_fgh<<<gFGH, 256>>>(style_sem,  Wg, bg, pMean + BB * CC, pIstd + BB * CC, pG, 1);
    gemm_fgh<<<gFGH, 256>>>(style,      Wh, bh, pMean, pIstd, pH, 0);
    gemm_score<<<gSCORE, 256>>>(pF, pG, pS);
    softmax_kernel<<<BB * NN, 256>>>(pS, map64);
    gemm_av<<<gAV, 256>>>(pS, pH, pO);

    // ---- SSA branch (content/style features, hard argmax == gather) ----
    stats_kernel<<<BB * CC, 256>>>(content, pMean, pIstd);
    stats_kernel<<<BB * CC, 256>>>(style, pMean + BB * CC, pIstd + BB * CC);
    gemm_fgh<<<gFGH, 256>>>(content, Wf, bf, pMean, pIstd, pF, 1);
    gemm_fgh<<<gFGH, 256>>>(style,   Wg, bg, pMean + BB * CC, pIstd + BB * CC, pG, 1);
    gemm_score<<<gSCORE, 256>>>(pF, pG, pS);
    argmax_kernel<<<BB * NN, 256>>>(pS, map64, pIdx);

    // ---- combine + output conv + residual ----
    combine_kernel<<<BB * NN, 256>>>(pO, pH, pIdx, t1p, t2p, pF);   // V -> g_F (reuse)
    gemm_final<<<gFGH, 256>>>(Wo, pF, bo, content, t1p, t2p, out);
}